// round 10
// baseline (speedup 1.0000x reference)
#include <cuda_runtime.h>
#include <cuda_bf16.h>

#define HH 28
#define WW 28
#define PAD 3
#define PW 35           // padded width (odd -> spread smem banks)
#define KK 7
#define NTAP 49
#define BATCH 512
#define NBR 8
#define FEAT 392        // 8 branches * 49

#define IMG_PER_BLK 4
#define STRIPS 56       // (28/7 cols) x (28/2 rows) strips per image
#define THREADS_A (IMG_PER_BLK * STRIPS)   // 224 = 7 full warps

typedef unsigned long long u64;
union F2U { float2 f; u64 u; };

__device__ float g_feat[BATCH * FEAT];
// float4-packed transposed weights: 4 consecutive K-steps per element.
__device__ float4 g_w1p[98 * 120];   // [i4][j]  w = W1[j][4*i4 .. 4*i4+3]
__device__ float4 g_w2p[30 * 84];    // [i4][j]
__device__ float4 g_w3p[21 * 10];    // [i4][j]
#define N_W1P (98 * 120)
#define N_W2P (30 * 84)
#define N_W3P (21 * 10)

#define FMA2(acc, a, b) asm("fma.rn.f32x2 %0, %1, %2, %0;" : "+l"(acc) : "l"(a), "l"(b))
#define PACK2(d, lo, hi) asm("mov.b64 %0, {%1, %2};" : "=l"(d) : "f"(lo), "f"(hi))
#define UNPK2(lo, hi, s) asm("mov.b64 {%0, %1}, %2;" : "=f"(lo), "=f"(hi) : "l"(s))

// SMorph factorization:  out = (sum c1*u + sum c2*v) / (sum c1*v)
// v = exp(a*x), u = x*v, c1 = exp(a*w), c2 = w*c1.  Zero SAME-pad <=> (v,u)=(1,0).
// One block = 4 images x 1 branch; thread owns a 7x2 output strip.
// Round-4 structure; the sum c2*v accumulators for the two strip rows are
// packed into one f32x2 chain (same per-row term order -> identical numerics).
__global__ void __launch_bounds__(THREADS_A)
smorph_branch_kernel(const float* __restrict__ x,
                     const float* __restrict__ sm_w,      // [8,2,7,7]
                     const float* __restrict__ sm_alpha,  // [8,2]
                     const float* __restrict__ W1,        // for folded repack
                     const float* __restrict__ W2,
                     const float* __restrict__ W3)
{
    extern __shared__ float smem[];
    float* svu  = smem;                              // [4][PW*PW][2]
    float* scp  = svu + IMG_PER_BLK * PW * PW * 2;   // [49] float2 (c1,c1)
    float* sc2p = scp + 2 * NTAP;                    // [56] float2 (c2[dy], c2[dy-1])

    const int tid = threadIdx.x;
    const int b0  = blockIdx.x * IMG_PER_BLK;
    const int r   = blockIdx.y;

    // ---- folded one-shot weight repack (float4 of 4 consecutive K-steps) ----
    {
        int gid = blockIdx.y * gridDim.x + blockIdx.x;
        int t = gid * THREADS_A + tid;
        if (t < N_W1P) {
            int i4 = t / 120, j = t % 120;
            g_w1p[t] = *(const float4*)(W1 + j * FEAT + 4 * i4);
        } else if (t < N_W1P + N_W2P) {
            int q = t - N_W1P; int i4 = q / 84, j = q % 84;
            g_w2p[q] = *(const float4*)(W2 + j * 120 + 4 * i4);
        } else if (t < N_W1P + N_W2P + N_W3P) {
            int q = t - N_W1P - N_W2P; int i4 = q / 10, j = q % 10;
            g_w3p[q] = *(const float4*)(W3 + j * 84 + 4 * i4);
        }
    }

    const int img = tid / STRIPS;
    const int s   = tid % STRIPS;
    const int pr0 = (s / 4) * 2;   // strip top row   (0..26)
    const int pc0 = (s % 4) * 7;   // strip left col  (0,7,14,21)

    float2* myvu = (float2*)svu + img * (PW * PW);
    const float* xim = x + (b0 + img) * (HH * WW);

    const float a0 = sm_alpha[r * 2 + 0];
    const float a1 = sm_alpha[r * 2 + 1];

    // init to halo (v,u)=(1,0); interior overwritten below
    {
        float2* p = (float2*)svu;
        for (int i = tid; i < IMG_PER_BLK * PW * PW; i += THREADS_A)
            p[i] = make_float2(1.0f, 0.0f);
    }
    // layer-0 coefficients: c1 pairs + c2 row-pair table
    if (tid < NTAP) {
        float wv = sm_w[(r * 2 + 0) * NTAP + tid];
        float c1 = __expf(a0 * wv);
        scp[2 * tid] = c1; scp[2 * tid + 1] = c1;
    }
    __syncthreads();
    if (tid < 56) {     // sc2p[dy*7+dx] = (c2[dy][dx] | 0, c2[dy-1][dx] | 0)
        int dy = tid / 7, dx = tid % 7;
        const float* wl = sm_w + (r * 2 + 0) * NTAP;
        float cur = 0.f, prv = 0.f;
        if (dy < 7) { float wv = wl[dy * 7 + dx]; cur = __expf(a0 * wv) * wv; }
        if (dy >= 1) { float wv = wl[(dy - 1) * 7 + dx]; prv = __expf(a0 * wv) * wv; }
        sc2p[2 * tid] = cur; sc2p[2 * tid + 1] = prv;
    }

    // layer-0 interior fill
    for (int i = s; i < HH * WW; i += STRIPS) {
        float xi = xim[i];
        float vv = __expf(a0 * xi);
        int pr = i / WW, pc = i % WW;
        myvu[(pr + PAD) * PW + pc + PAD] = make_float2(vv, xi * vv);
    }
    __syncthreads();

    float y[2][7];

    #pragma unroll 1
    for (int L = 0; L < 2; L++) {
        u64 acc2[2][7];   // packed (den = sum c1*v, num_u = sum c1*u)
        u64 accw[7];      // packed (sum c2*v for sr0, sr1)
        #pragma unroll
        for (int j = 0; j < 7; j++) { acc2[0][j] = 0ull; acc2[1][j] = 0ull; accw[j] = 0ull; }

        F2U cc_cur[7], cc_prev[7];

        #pragma unroll
        for (int dy = 0; dy < 8; dy++) {
            F2U t[13];
            const float2* rowp = myvu + (pr0 + dy) * PW + pc0;
            #pragma unroll
            for (int k = 0; k < 13; k++) t[k].f = rowp[k];

            // (v,v) packs for the row-paired c2 accumulation
            u64 vv2[13];
            #pragma unroll
            for (int k = 0; k < 13; k++) PACK2(vv2[k], t[k].f.x, t[k].f.x);

            if (dy < 7) {
                #pragma unroll
                for (int dx = 0; dx < 7; dx++)
                    cc_cur[dx].f = ((const float2*)scp)[dy * 7 + dx];
                // sr = 0 uses tap row ky = dy
                #pragma unroll
                for (int dx = 0; dx < 7; dx++) {
                    u64 c = cc_cur[dx].u;
                    #pragma unroll
                    for (int scx = 0; scx < 7; scx++)
                        FMA2(acc2[0][scx], c, t[dx + scx].u);
                }
            }
            if (dy >= 1) {
                // sr = 1 uses tap row ky = dy-1 (cached from previous iteration)
                #pragma unroll
                for (int dx = 0; dx < 7; dx++) {
                    u64 c = cc_prev[dx].u;
                    #pragma unroll
                    for (int scx = 0; scx < 7; scx++)
                        FMA2(acc2[1][scx], c, t[dx + scx].u);
                }
            }
            // paired c2 pass: accw += (c2[dy],c2[dy-1]) * (v,v)
            #pragma unroll
            for (int dx = 0; dx < 7; dx++) {
                u64 c2p = ((const u64*)sc2p)[dy * 7 + dx];
                #pragma unroll
                for (int scx = 0; scx < 7; scx++)
                    FMA2(accw[scx], c2p, vv2[dx + scx]);
            }
            if (dy < 7) {
                #pragma unroll
                for (int dx = 0; dx < 7; dx++) cc_prev[dx] = cc_cur[dx];
            }
        }

        #pragma unroll
        for (int scx = 0; scx < 7; scx++) {
            float w0, w1;
            UNPK2(w0, w1, accw[scx]);
            F2U a0u; a0u.u = acc2[0][scx];
            F2U a1u; a1u.u = acc2[1][scx];
            y[0][scx] = __fdividef(a0u.f.y + w0, a0u.f.x);
            y[1][scx] = __fdividef(a1u.f.y + w1, a1u.f.x);
        }
        __syncthreads();   // all conv reads of svu / coeff smem done

        if (L == 0) {
            // refresh coefficients for layer 1
            if (tid < NTAP) {
                float wv = sm_w[(r * 2 + 1) * NTAP + tid];
                float c1 = __expf(a1 * wv);
                scp[2 * tid] = c1; scp[2 * tid + 1] = c1;
            }
            if (tid < 56) {
                int dy = tid / 7, dx = tid % 7;
                const float* wl = sm_w + (r * 2 + 1) * NTAP;
                float cur = 0.f, prv = 0.f;
                if (dy < 7) { float wv = wl[dy * 7 + dx]; cur = __expf(a1 * wv) * wv; }
                if (dy >= 1) { float wv = wl[(dy - 1) * 7 + dx]; prv = __expf(a1 * wv) * wv; }
                sc2p[2 * tid] = cur; sc2p[2 * tid + 1] = prv;
            }
            #pragma unroll
            for (int sr = 0; sr < 2; sr++)
                #pragma unroll
                for (int scx = 0; scx < 7; scx++) {
                    float yi = y[sr][scx];
                    float vv = __expf(a1 * yi);
                    myvu[(pr0 + sr + PAD) * PW + pc0 + scx + PAD] =
                        make_float2(vv, yi * vv);
                }
        } else {
            // final layer: store y as plain floats overlaid on this image's svu
            float* syf = (float*)myvu;
            #pragma unroll
            for (int sr = 0; sr < 2; sr++)
                #pragma unroll
                for (int scx = 0; scx < 7; scx++)
                    syf[(pr0 + sr) * WW + pc0 + scx] = y[sr][scx];
        }
        __syncthreads();
    }

    // ---- 4x4 avg pool (== two 2x2 pools) -> [7,7] features ----
    if (s < NTAP) {
        const float* syf = (const float*)myvu;
        int qr = s / 7, qc = s % 7;
        float acc = 0.0f;
        #pragma unroll
        for (int dy = 0; dy < 4; dy++)
            #pragma unroll
            for (int dx = 0; dx < 4; dx++)
                acc += syf[(qr * 4 + dy) * WW + qc * 4 + dx];
        g_feat[(b0 + img) * FEAT + r * NTAP + s] = acc * (1.0f / 16.0f);
    }
}

__device__ __forceinline__ float sigf(float z) {
    return 1.0f / (1.0f + __expf(-z));
}

// Fused 3-layer sigmoid MLP with ALL weights smem-resident.
// 128 blocks x 256 threads, 4 batch rows per block (2 row-groups of 2).
// Per-row fmaf nesting/order identical to Round 4 (rel_err 7.4e-8).
#define MROWS 4
#define MLP_SMEM_BYTES ((N_W1P + N_W3P) * 16 + (MROWS * (FEAT + 120 + 84)) * 4)

#define MLP_GROUP4(GW, SA, SB, I4, STRIDE)                                         \
    {                                                                              \
        float4 w0 = GW[(I4 + 0) * STRIDE + j];                                     \
        float4 w1 = GW[(I4 + 1) * STRIDE + j];                                     \
        float4 w2 = GW[(I4 + 2) * STRIDE + j];                                     \
        float4 w3 = GW[(I4 + 3) * STRIDE + j];                                     \
        float4 sa0 = *(const float4*)&SA[(I4 + 0) * 4];                            \
        float4 sb0 = *(const float4*)&SB[(I4 + 0) * 4];                            \
        float4 sa1 = *(const float4*)&SA[(I4 + 1) * 4];                            \
        float4 sb1 = *(const float4*)&SB[(I4 + 1) * 4];                            \
        float4 sa2 = *(const float4*)&SA[(I4 + 2) * 4];                            \
        float4 sb2 = *(const float4*)&SB[(I4 + 2) * 4];                            \
        float4 sa3 = *(const float4*)&SA[(I4 + 3) * 4];                            \
        float4 sb3 = *(const float4*)&SB[(I4 + 3) * 4];                            \
        accA = fmaf(w0.x, sa0.x, fmaf(w0.y, sa0.y, fmaf(w0.z, sa0.z, fmaf(w0.w, sa0.w, accA)))); \
        accB = fmaf(w0.x, sb0.x, fmaf(w0.y, sb0.y, fmaf(w0.z, sb0.z, fmaf(w0.w, sb0.w, accB)))); \
        accA = fmaf(w1.x, sa1.x, fmaf(w1.y, sa1.y, fmaf(w1.z, sa1.z, fmaf(w1.w, sa1.w, accA)))); \
        accB = fmaf(w1.x, sb1.x, fmaf(w1.y, sb1.y, fmaf(w1.z, sb1.z, fmaf(w1.w, sb1.w, accB)))); \
        accA = fmaf(w2.x, sa2.x, fmaf(w2.y, sa2.y, fmaf(w2.z, sa2.z, fmaf(w2.w, sa2.w, accA)))); \
        accB = fmaf(w2.x, sb2.x, fmaf(w2.y, sb2.y, fmaf(w2.z, sb2.z, fmaf(w2.w, sb2.w, accB)))); \
        accA = fmaf(w3.x, sa3.x, fmaf(w3.y, sa3.y, fmaf(w3.z, sa3.z, fmaf(w3.w, sa3.w, accA)))); \
        accB = fmaf(w3.x, sb3.x, fmaf(w3.y, sb3.y, fmaf(w3.z, sb3.z, fmaf(w3.w, sb3.w, accB)))); \
    }

__global__ void __launch_bounds__(256) mlp_kernel(
    const float* __restrict__ b1,
    const float* __restrict__ b2,
    const float* __restrict__ b3,
    float* __restrict__ out)
{
    extern __shared__ float4 mlp_smem[];
    float4* swb = mlp_smem;                    // N_W1P (reused for W2)
    float4* sw3 = swb + N_W1P;                 // N_W3P
    float*  sf  = (float*)(sw3 + N_W3P);       // [MROWS][FEAT]
    float*  sh1 = sf + MROWS * FEAT;           // [MROWS][120]
    float*  sh2 = sh1 + MROWS * 120;           // [MROWS][84]

    const int tid = threadIdx.x;
    const int b0  = blockIdx.x * MROWS;
    const int j   = tid & 127;           // output-neuron lane
    const int rg  = tid >> 7;            // 0..1
    const int rA  = rg * 2, rB = rA + 1;

    // ---- stage W1, W3, features (all loads independent) ----
    for (int i = tid; i < N_W1P; i += 256) swb[i] = g_w1p[i];
    if (tid < N_W3P) sw3[tid] = g_w3p[tid];
    {
        const float4* src = (const float4*)(g_feat + b0 * FEAT);
        #pragma unroll
        for (int i = tid; i < MROWS * FEAT / 4; i += 256)
            ((float4*)sf)[i] = src[i];
    }
    __syncthreads();

    // ---- 392 -> 120 : 98 i4-groups = 24x4 + 2 ----
    if (j < 120) {
        float bb = b1[j];
        float accA = bb, accB = bb;
        const float* SA = sf + rA * FEAT;
        const float* SB = sf + rB * FEAT;
        #pragma unroll 6
        for (int g = 0; g < 24; g++)
            MLP_GROUP4(swb, SA, SB, g * 4, 120)
        #pragma unroll
        for (int i4 = 96; i4 < 98; i4++) {
            float4 w  = swb[i4 * 120 + j];
            float4 sa = *(const float4*)&SA[i4 * 4];
            float4 sb = *(const float4*)&SB[i4 * 4];
            accA = fmaf(w.x, sa.x, fmaf(w.y, sa.y, fmaf(w.z, sa.z, fmaf(w.w, sa.w, accA))));
            accB = fmaf(w.x, sb.x, fmaf(w.y, sb.y, fmaf(w.z, sb.z, fmaf(w.w, sb.w, accB))));
        }
        sh1[rA * 120 + j] = sigf(accA);
        sh1[rB * 120 + j] = sigf(accB);
    }
    __syncthreads();

    // ---- restage W2 over W1's buffer ----
    for (int i = tid; i < N_W2P; i += 256) swb[i] = g_w2p[i];
    __syncthreads();

    // ---- 120 -> 84 : 30 i4-groups = 7x4 + 2 ----
    if (j < 84) {
        float bb = b2[j];
        float accA = bb, accB = bb;
        const float* SA = sh1 + rA * 120;
        const float* SB = sh1 + rB * 120;
        #pragma unroll 7
        for (int g = 0; g < 7; g++)
            MLP_GROUP4(swb, SA, SB, g * 4, 84)
        #pragma unroll
        for (int i4 = 28; i4 < 30; i4++) {
            float4 w  = swb[i4 * 84 + j];
            float4 sa = *(const float4*)&SA[i4 * 4];
            float4 sb = *(const float4*)&SB[i4 * 4];
            accA = fmaf(w.x, sa.x, fmaf(w.y, sa.y, fmaf(w.z, sa.z, fmaf(w.w, sa.w, accA))));
            accB = fmaf(w.x, sb.x, fmaf(w.y, sb.y, fmaf(w.z, sb.z, fmaf(w.w, sb.w, accB))));
        }
        sh2[rA * 84 + j] = sigf(accA);
        sh2[rB * 84 + j] = sigf(accB);
    }
    __syncthreads();

    // ---- 84 -> 10 ----  (40 threads: one (row, j) scalar dot each)
    if (tid < 40) {
        const int jj = tid % 10;
        const int rr = tid / 10;
        float acc = b3[jj];
        const float* S = sh2 + rr * 84;
        #pragma unroll 7
        for (int i4 = 0; i4 < 21; i4++) {
            float4 w = sw3[i4 * 10 + jj];
            float4 s = *(const float4*)&S[i4 * 4];
            acc = fmaf(w.x, s.x, fmaf(w.y, s.y, fmaf(w.z, s.z, fmaf(w.w, s.w, acc))));
        }
        out[(b0 + rr) * 10 + jj] = sigf(acc);
    }
}

extern "C" void kernel_launch(void* const* d_in, const int* in_sizes, int n_in,
                              void* d_out, int out_size)
{
    const float* x        = (const float*)d_in[0];
    const float* sm_w     = (const float*)d_in[1];
    const float* sm_alpha = (const float*)d_in[2];
    const float* W1       = (const float*)d_in[3];
    const float* b1       = (const float*)d_in[4];
    const float* W2       = (const float*)d_in[5];
    const float* b2       = (const float*)d_in[6];
    const float* W3       = (const float*)d_in[7];
    const float* b3       = (const float*)d_in[8];
    float* out = (float*)d_out;

    static int attr_done = 0;
    if (!attr_done) {
        cudaFuncSetAttribute(mlp_kernel,
                             cudaFuncAttributeMaxDynamicSharedMemorySize,
                             MLP_SMEM_BYTES);
        attr_done = 1;
    }

    const int smem_bytes =
        (IMG_PER_BLK * PW * PW * 2 + 2 * NTAP + 2 * 56) * (int)sizeof(float);

    dim3 gridA(BATCH / IMG_PER_BLK, NBR);   // (128, 8)
    smorph_branch_kernel<<<gridA, THREADS_A, smem_bytes>>>(
        x, sm_w, sm_alpha, W1, W2, W3);

    mlp_kernel<<<BATCH / MROWS, 256, MLP_SMEM_BYTES>>>(b1, b2, b3, out);
}

// round 11
// speedup vs baseline: 1.0511x; 1.0511x over previous
#include <cuda_runtime.h>
#include <cuda_bf16.h>

#define HH 28
#define WW 28
#define PAD 3
#define PW 35           // padded width (floats-of-float2, odd -> spread banks)
#define NPX (PW * PW)   // 1225 float2 cells per plane
#define KK 7
#define NTAP 49
#define BATCH 512
#define NBR 8
#define FEAT 392        // 8 branches * 49

#define PAIRS_PER_BLK 2                    // 2 image pairs = 4 images
#define STRIPS 112                         // 28 rows x 4 col-strips of 7
#define THREADS_A (PAIRS_PER_BLK * STRIPS) // 224 = 7 full warps

typedef unsigned long long u64;
union F2U { float2 f; u64 u; };

__device__ float g_feat[BATCH * FEAT];
// float4-packed transposed weights: 4 consecutive K-steps per element.
__device__ float4 g_w1p[98 * 120];   // [i4][j]  w = W1[j][4*i4 .. 4*i4+3]
__device__ float4 g_w2p[30 * 84];    // [i4][j]
__device__ float4 g_w3p[21 * 10];    // [i4][j]
#define N_W1P (98 * 120)
#define N_W2P (30 * 84)
#define N_W3P (21 * 10)

#define FMA2(acc, a, b) asm("fma.rn.f32x2 %0, %1, %2, %0;" : "+l"(acc) : "l"(a), "l"(b))

// SMorph factorization:  out = (sum c1*u + sum c2*v) / (sum c1*v)
// v = exp(a*x), u = x*v, c1 = exp(a*w), c2 = w*c1.  Zero SAME-pad <=> (v,u)=(1,0).
//
// IMAGE-PAIR vectorization: shared planes hold (vA,vB) / (uA,uB) float2 per
// pixel; every tap is 3 f32x2 FMAs serving BOTH images (1.5 fma-slots per
// tap-image, no repacking). Each lane accumulates its image in exactly the
// Round-4 term order (dy-major, dx-inner) -> numerics identical.
// One block = 2 image pairs (4 images) x 1 branch; thread owns a 7x1 strip.
__global__ void __launch_bounds__(THREADS_A)
smorph_branch_kernel(const float* __restrict__ x,
                     const float* __restrict__ sm_w,      // [8,2,7,7]
                     const float* __restrict__ sm_alpha,  // [8,2]
                     const float* __restrict__ W1,        // for folded repack
                     const float* __restrict__ W2,
                     const float* __restrict__ W3)
{
    extern __shared__ float2 smem2[];
    // [pair][2 planes][NPX]: v plane then u plane per pair; coeff tables after
    float2* base = smem2;
    float2* sc1  = smem2 + PAIRS_PER_BLK * 2 * NPX;   // [49] (c1,c1)
    float2* sc2  = sc1 + NTAP;                        // [49] (c2,c2)

    const int tid = threadIdx.x;
    const int b0  = blockIdx.x * (PAIRS_PER_BLK * 2);  // 4 images
    const int r   = blockIdx.y;

    // ---- folded one-shot weight repack (float4 of 4 consecutive K-steps) ----
    {
        int gid = blockIdx.y * gridDim.x + blockIdx.x;
        int t = gid * THREADS_A + tid;
        if (t < N_W1P) {
            int i4 = t / 120, j = t % 120;
            g_w1p[t] = *(const float4*)(W1 + j * FEAT + 4 * i4);
        } else if (t < N_W1P + N_W2P) {
            int q = t - N_W1P; int i4 = q / 84, j = q % 84;
            g_w2p[q] = *(const float4*)(W2 + j * 120 + 4 * i4);
        } else if (t < N_W1P + N_W2P + N_W3P) {
            int q = t - N_W1P - N_W2P; int i4 = q / 10, j = q % 10;
            g_w3p[q] = *(const float4*)(W3 + j * 84 + 4 * i4);
        }
    }

    const int pairId = tid / STRIPS;          // 0..1
    const int s      = tid % STRIPS;          // 0..111
    const int pr     = s >> 2;                // output row 0..27
    const int pc0    = (s & 3) * 7;           // strip left col 0,7,14,21

    float2* vab = base + pairId * (2 * NPX);
    float2* uab = vab + NPX;
    const float* xA = x + (b0 + 2 * pairId + 0) * (HH * WW);
    const float* xB = x + (b0 + 2 * pairId + 1) * (HH * WW);

    const float a0 = sm_alpha[r * 2 + 0];
    const float a1 = sm_alpha[r * 2 + 1];

    // halo init: v=(1,1), u=(0,0) everywhere; interior overwritten below
    for (int i = tid; i < PAIRS_PER_BLK * 2 * NPX; i += THREADS_A) {
        bool isV = ((i / NPX) & 1) == 0;
        base[i] = isV ? make_float2(1.0f, 1.0f) : make_float2(0.0f, 0.0f);
    }
    // layer-0 coefficient tables
    if (tid < NTAP) {
        float wv = sm_w[(r * 2 + 0) * NTAP + tid];
        float c1 = __expf(a0 * wv);
        float c2 = c1 * wv;
        sc1[tid] = make_float2(c1, c1);
        sc2[tid] = make_float2(c2, c2);
    }
    __syncthreads();

    // layer-0 interior fill (both images of the pair)
    for (int i = s; i < HH * WW; i += STRIPS) {
        float xa = xA[i], xb = xB[i];
        float va = __expf(a0 * xa), vb = __expf(a0 * xb);
        int idx = (i / WW + PAD) * PW + (i % WW) + PAD;
        vab[idx] = make_float2(va, vb);
        uab[idx] = make_float2(xa * va, xb * vb);
    }
    __syncthreads();

    const u64* c1p = (const u64*)sc1;
    const u64* c2p = (const u64*)sc2;

    float2 y[7];

    #pragma unroll 1
    for (int L = 0; L < 2; L++) {
        u64 accD[7], accU[7], accW[7];
        #pragma unroll
        for (int m = 0; m < 7; m++) { accD[m] = 0ull; accU[m] = 0ull; accW[m] = 0ull; }

        #pragma unroll
        for (int dy = 0; dy < 7; dy++) {
            const int rb = (pr + dy) * PW + pc0;
            F2U vw[13], uw[13];
            #pragma unroll
            for (int k = 0; k < 13; k++) vw[k].f = vab[rb + k];
            #pragma unroll
            for (int k = 0; k < 13; k++) uw[k].f = uab[rb + k];

            #pragma unroll
            for (int dx = 0; dx < 7; dx++) {
                const u64 c1 = c1p[dy * 7 + dx];
                const u64 c2 = c2p[dy * 7 + dx];
                #pragma unroll
                for (int m = 0; m < 7; m++) {
                    FMA2(accD[m], c1, vw[dx + m].u);
                    FMA2(accU[m], c1, uw[dx + m].u);
                    FMA2(accW[m], c2, vw[dx + m].u);
                }
            }
        }

        #pragma unroll
        for (int m = 0; m < 7; m++) {
            F2U d, nu, nw;
            d.u = accD[m]; nu.u = accU[m]; nw.u = accW[m];
            y[m].x = __fdividef(nu.f.x + nw.f.x, d.f.x);
            y[m].y = __fdividef(nu.f.y + nw.f.y, d.f.y);
        }
        __syncthreads();   // all conv reads of planes / coeffs done

        if (L == 0) {
            // refresh coefficients for layer 1
            if (tid < NTAP) {
                float wv = sm_w[(r * 2 + 1) * NTAP + tid];
                float c1 = __expf(a1 * wv);
                float c2 = c1 * wv;
                sc1[tid] = make_float2(c1, c1);
                sc2[tid] = make_float2(c2, c2);
            }
            // write layer-1 (v,u) pairs directly
            #pragma unroll
            for (int m = 0; m < 7; m++) {
                float ya = y[m].x, yb = y[m].y;
                float va = __expf(a1 * ya), vb = __expf(a1 * yb);
                int idx = (pr + PAD) * PW + pc0 + m + PAD;
                vab[idx] = make_float2(va, vb);
                uab[idx] = make_float2(ya * va, yb * vb);
            }
        } else {
            // final layer: store y pairs overlaid on this pair's u-plane
            #pragma unroll
            for (int m = 0; m < 7; m++)
                uab[pr * WW + pc0 + m] = y[m];
        }
        __syncthreads();
    }

    // ---- 4x4 avg pool -> [7,7] features for both images of the pair ----
    if (s < NTAP) {
        int qr = s / 7, qc = s % 7;
        float accA = 0.0f, accB = 0.0f;
        #pragma unroll
        for (int dy = 0; dy < 4; dy++)
            #pragma unroll
            for (int dx = 0; dx < 4; dx++) {
                float2 p = uab[(qr * 4 + dy) * WW + qc * 4 + dx];
                accA += p.x; accB += p.y;
            }
        g_feat[(b0 + 2 * pairId + 0) * FEAT + r * NTAP + s] = accA * (1.0f / 16.0f);
        g_feat[(b0 + 2 * pairId + 1) * FEAT + r * NTAP + s] = accB * (1.0f / 16.0f);
    }
}

__device__ __forceinline__ float sigf(float z) {
    return 1.0f / (1.0f + __expf(-z));
}

// Fused 3-layer sigmoid MLP with ALL weights smem-resident.
// 128 blocks x 256 threads, 4 batch rows per block (2 row-groups of 2).
// Per-row fmaf nesting/order identical to Round 4 (rel_err 7.4e-8).
#define MROWS 4
#define MLP_SMEM_BYTES ((N_W1P + N_W3P) * 16 + (MROWS * (FEAT + 120 + 84)) * 4)

#define MLP_GROUP4(GW, SA, SB, I4, STRIDE)                                         \
    {                                                                              \
        float4 w0 = GW[(I4 + 0) * STRIDE + j];                                     \
        float4 w1 = GW[(I4 + 1) * STRIDE + j];                                     \
        float4 w2 = GW[(I4 + 2) * STRIDE + j];                                     \
        float4 w3 = GW[(I4 + 3) * STRIDE + j];                                     \
        float4 sa0 = *(const float4*)&SA[(I4 + 0) * 4];                            \
        float4 sb0 = *(const float4*)&SB[(I4 + 0) * 4];                            \
        float4 sa1 = *(const float4*)&SA[(I4 + 1) * 4];                            \
        float4 sb1 = *(const float4*)&SB[(I4 + 1) * 4];                            \
        float4 sa2 = *(const float4*)&SA[(I4 + 2) * 4];                            \
        float4 sb2 = *(const float4*)&SB[(I4 + 2) * 4];                            \
        float4 sa3 = *(const float4*)&SA[(I4 + 3) * 4];                            \
        float4 sb3 = *(const float4*)&SB[(I4 + 3) * 4];                            \
        accA = fmaf(w0.x, sa0.x, fmaf(w0.y, sa0.y, fmaf(w0.z, sa0.z, fmaf(w0.w, sa0.w, accA)))); \
        accB = fmaf(w0.x, sb0.x, fmaf(w0.y, sb0.y, fmaf(w0.z, sb0.z, fmaf(w0.w, sb0.w, accB)))); \
        accA = fmaf(w1.x, sa1.x, fmaf(w1.y, sa1.y, fmaf(w1.z, sa1.z, fmaf(w1.w, sa1.w, accA)))); \
        accB = fmaf(w1.x, sb1.x, fmaf(w1.y, sb1.y, fmaf(w1.z, sb1.z, fmaf(w1.w, sb1.w, accB)))); \
        accA = fmaf(w2.x, sa2.x, fmaf(w2.y, sa2.y, fmaf(w2.z, sa2.z, fmaf(w2.w, sa2.w, accA)))); \
        accB = fmaf(w2.x, sb2.x, fmaf(w2.y, sb2.y, fmaf(w2.z, sb2.z, fmaf(w2.w, sb2.w, accB)))); \
        accA = fmaf(w3.x, sa3.x, fmaf(w3.y, sa3.y, fmaf(w3.z, sa3.z, fmaf(w3.w, sa3.w, accA)))); \
        accB = fmaf(w3.x, sb3.x, fmaf(w3.y, sb3.y, fmaf(w3.z, sb3.z, fmaf(w3.w, sb3.w, accB)))); \
    }

__global__ void __launch_bounds__(256) mlp_kernel(
    const float* __restrict__ b1,
    const float* __restrict__ b2,
    const float* __restrict__ b3,
    float* __restrict__ out)
{
    extern __shared__ float4 mlp_smem[];
    float4* swb = mlp_smem;                    // N_W1P (reused for W2)
    float4* sw3 = swb + N_W1P;                 // N_W3P
    float*  sf  = (float*)(sw3 + N_W3P);       // [MROWS][FEAT]
    float*  sh1 = sf + MROWS * FEAT;           // [MROWS][120]
    float*  sh2 = sh1 + MROWS * 120;           // [MROWS][84]

    const int tid = threadIdx.x;
    const int b0  = blockIdx.x * MROWS;
    const int j   = tid & 127;           // output-neuron lane
    const int rg  = tid >> 7;            // 0..1
    const int rA  = rg * 2, rB = rA + 1;

    // ---- stage W1, W3, features (all loads independent) ----
    for (int i = tid; i < N_W1P; i += 256) swb[i] = g_w1p[i];
    if (tid < N_W3P) sw3[tid] = g_w3p[tid];
    {
        const float4* src = (const float4*)(g_feat + b0 * FEAT);
        #pragma unroll
        for (int i = tid; i < MROWS * FEAT / 4; i += 256)
            ((float4*)sf)[i] = src[i];
    }
    __syncthreads();

    // ---- 392 -> 120 : 98 i4-groups = 24x4 + 2 ----
    if (j < 120) {
        float bb = b1[j];
        float accA = bb, accB = bb;
        const float* SA = sf + rA * FEAT;
        const float* SB = sf + rB * FEAT;
        #pragma unroll 6
        for (int g = 0; g < 24; g++)
            MLP_GROUP4(swb, SA, SB, g * 4, 120)
        #pragma unroll
        for (int i4 = 96; i4 < 98; i4++) {
            float4 w  = swb[i4 * 120 + j];
            float4 sa = *(const float4*)&SA[i4 * 4];
            float4 sb = *(const float4*)&SB[i4 * 4];
            accA = fmaf(w.x, sa.x, fmaf(w.y, sa.y, fmaf(w.z, sa.z, fmaf(w.w, sa.w, accA))));
            accB = fmaf(w.x, sb.x, fmaf(w.y, sb.y, fmaf(w.z, sb.z, fmaf(w.w, sb.w, accB))));
        }
        sh1[rA * 120 + j] = sigf(accA);
        sh1[rB * 120 + j] = sigf(accB);
    }
    __syncthreads();

    // ---- restage W2 over W1's buffer ----
    for (int i = tid; i < N_W2P; i += 256) swb[i] = g_w2p[i];
    __syncthreads();

    // ---- 120 -> 84 : 30 i4-groups = 7x4 + 2 ----
    if (j < 84) {
        float bb = b2[j];
        float accA = bb, accB = bb;
        const float* SA = sh1 + rA * 120;
        const float* SB = sh1 + rB * 120;
        #pragma unroll 7
        for (int g = 0; g < 7; g++)
            MLP_GROUP4(swb, SA, SB, g * 4, 84)
        #pragma unroll
        for (int i4 = 28; i4 < 30; i4++) {
            float4 w  = swb[i4 * 84 + j];
            float4 sa = *(const float4*)&SA[i4 * 4];
            float4 sb = *(const float4*)&SB[i4 * 4];
            accA = fmaf(w.x, sa.x, fmaf(w.y, sa.y, fmaf(w.z, sa.z, fmaf(w.w, sa.w, accA))));
            accB = fmaf(w.x, sb.x, fmaf(w.y, sb.y, fmaf(w.z, sb.z, fmaf(w.w, sb.w, accB))));
        }
        sh2[rA * 84 + j] = sigf(accA);
        sh2[rB * 84 + j] = sigf(accB);
    }
    __syncthreads();

    // ---- 84 -> 10 ----  (40 threads: one (row, j) scalar dot each)
    if (tid < 40) {
        const int jj = tid % 10;
        const int rr = tid / 10;
        float acc = b3[jj];
        const float* S = sh2 + rr * 84;
        #pragma unroll 7
        for (int i4 = 0; i4 < 21; i4++) {
            float4 w = sw3[i4 * 10 + jj];
            float4 s = *(const float4*)&S[i4 * 4];
            acc = fmaf(w.x, s.x, fmaf(w.y, s.y, fmaf(w.z, s.z, fmaf(w.w, s.w, acc))));
        }
        out[(b0 + rr) * 10 + jj] = sigf(acc);
    }
}

extern "C" void kernel_launch(void* const* d_in, const int* in_sizes, int n_in,
                              void* d_out, int out_size)
{
    const float* x        = (const float*)d_in[0];
    const float* sm_w     = (const float*)d_in[1];
    const float* sm_alpha = (const float*)d_in[2];
    const float* W1       = (const float*)d_in[3];
    const float* b1       = (const float*)d_in[4];
    const float* W2       = (const float*)d_in[5];
    const float* b2       = (const float*)d_in[6];
    const float* W3       = (const float*)d_in[7];
    const float* b3       = (const float*)d_in[8];
    float* out = (float*)d_out;

    static int attr_done = 0;
    if (!attr_done) {
        cudaFuncSetAttribute(mlp_kernel,
                             cudaFuncAttributeMaxDynamicSharedMemorySize,
                             MLP_SMEM_BYTES);
        attr_done = 1;
    }

    const int smorph_smem =
        (PAIRS_PER_BLK * 2 * NPX + 2 * NTAP) * (int)sizeof(float2);  // ~40KB

    dim3 gridA(BATCH / (PAIRS_PER_BLK * 2), NBR);   // (128, 8)
    smorph_branch_kernel<<<gridA, THREADS_A, smorph_smem>>>(
        x, sm_w, sm_alpha, W1, W2, W3);

    mlp_kernel<<<BATCH / MROWS, 256, MLP_SMEM_BYTES>>>(b1, b2, b3, out);
}